// round 13
// baseline (speedup 1.0000x reference)
#include <cuda_runtime.h>
#include <cstdint>

#define NB      8
#define NCH     3
#define IMG     1024
#define PATCH   128
#define DPOS    256
#define KSEL    16
#define NSAMP   500
#define HGRID   16
#define WGRID   16
#define NKB     4          // k blocks
#define KPB     4          // k per block
#define NBLK    (32 * NCH * NB)   // assemble grid size = 768

typedef unsigned long long ull;

// Persistent device scratch (zero-init at load; the LAST assemble block
// re-zeroes d_counts and resets d_done -> clean state every graph replay).
__device__ __align__(16) int d_counts[NB][KSEL][DPOS];
__device__ int d_done;

// ---------------------------------------------------------------------------
// Threefry-2x32 (20 rounds), JAX partitionable layout:
//   bits[f] = o0 ^ o1 of E(key=(0,42), ctr=(hi=0, lo=f))
// ---------------------------------------------------------------------------
__device__ __forceinline__ uint32_t threefry_bits(uint32_t ctr) {
    const uint32_t K0 = 0u;
    const uint32_t K1 = 42u;
    const uint32_t K2 = 0x1BD11BDAu ^ K0 ^ K1;
    uint32_t x0 = K0;
    uint32_t x1 = ctr + K1;
#define TFR(r) { x0 += x1; x1 = __funnelshift_l(x1, x1, (r)); x1 ^= x0; }
    TFR(13) TFR(15) TFR(26) TFR(6)
    x0 += K1; x1 += K2 + 1u;
    TFR(17) TFR(29) TFR(16) TFR(24)
    x0 += K2; x1 += K0 + 2u;
    TFR(13) TFR(15) TFR(26) TFR(6)
    x0 += K0; x1 += K1 + 3u;
    TFR(17) TFR(29) TFR(16) TFR(24)
    x0 += K1; x1 += K2 + 4u;
    TFR(13) TFR(15) TFR(26) TFR(6)
    x0 += K2; x1 += K0 + 5u;
#undef TFR
    return x0 ^ x1;
}

__device__ __forceinline__ float jax_normal(uint32_t f) {
    uint32_t bits = threefry_bits(f);
    float fl = __uint_as_float((bits >> 9) | 0x3f800000u) - 1.0f;  // [0,1)
    const float lo = -0.99999994f;
    float u = fl * 2.0f + lo;
    u = fmaxf(lo, u);
    return __uint_as_float(0x3fb504f3u) * erfinvf(u);   // sqrt(2)*erfinv
}

// monotone float -> sortable u32 (strictly order-preserving)
__device__ __forceinline__ uint32_t fkey(float v) {
    uint32_t u = __float_as_uint(v);
    return u ^ (uint32_t)(((int)u >> 31) | 0x80000000);
}

// ---------------------------------------------------------------------------
// Kernel 1: perturbed top-K counting; fused normalization; 1 sample/warp,
// REDUX-based selection. grid = (125, NB), block = 128 (4 warps).
// ---------------------------------------------------------------------------
__global__ void indicator_kernel(const float* __restrict__ scores) {
    __shared__ float s_sh[DPOS];
    __shared__ float red[64];
    int b = blockIdx.y;
    int t = threadIdx.x;
    int warp = t >> 5, lane = t & 31;

    // per-batch min/max normalize (redundant per block; trivial)
    float v0 = __ldg(scores + b * DPOS + t);
    float v1 = __ldg(scores + b * DPOS + 128 + t);
    float mn = fminf(v0, v1), mx = fmaxf(v0, v1);
#pragma unroll
    for (int off = 16; off; off >>= 1) {
        mn = fminf(mn, __shfl_down_sync(0xffffffffu, mn, off));
        mx = fmaxf(mx, __shfl_down_sync(0xffffffffu, mx, off));
    }
    if (lane == 0) { red[warp] = mn; red[32 + warp] = mx; }
    __syncthreads();
    if (t == 0) {
        float m0 = red[0], m1 = red[32];
#pragma unroll
        for (int j = 1; j < 4; j++) { m0 = fminf(m0, red[j]); m1 = fmaxf(m1, red[32 + j]); }
        red[0] = m0; red[32] = m1;
    }
    __syncthreads();
    mn = red[0]; mx = red[32];
    float den = (mx - mn) + 1e-5f;
    s_sh[t]       = __fdiv_rn(v0 - mn, den);
    s_sh[t + 128] = __fdiv_rn(v1 - mn, den);
    __syncthreads();

    int sample = blockIdx.x * 4 + warp;            // 0..499
    uint32_t base = (uint32_t)((b * NSAMP + sample) * DPOS);

    uint32_t ka[8];
#pragma unroll
    for (int j = 0; j < 8; j++) {
        int pos = j * 32 + lane;
        float z = jax_normal(base + (uint32_t)pos);
        ka[j] = fkey(__fadd_rn(s_sh[pos], __fmul_rn(z, 0.05f)));
    }

    int sel = 0;
    for (int it = 0; it < KSEL; it++) {
        uint32_t bk = 0u;
        int bp = 0x7fffffff;
#pragma unroll
        for (int j = 0; j < 8; j++) {
            int pos = j * 32 + lane;
            if (ka[j] > bk) { bk = ka[j]; bp = pos; }
        }
        uint32_t m = __reduce_max_sync(0xffffffffu, bk);
        unsigned cand = (bk == m) ? (unsigned)bp : 0x7fffffffu;
        int w = (int)__reduce_min_sync(0xffffffffu, cand);
        int sj = w >> 5;
        if (lane == (w & 31)) {
#pragma unroll
            for (int j = 0; j < 8; j++) if (j == sj) ka[j] = 0u;
        }
        if (lane == it) sel = w;
    }

    // rank = index order among the 16 selections
    int r = 0;
#pragma unroll
    for (int j = 0; j < KSEL; j++) {
        int o = __shfl_sync(0xffffffffu, sel, j);
        if (o < sel) r++;
    }
    if (lane < KSEL) atomicAdd(&d_counts[b][r][sel], 1);
}

// ---------------------------------------------------------------------------
// Kernel 2 (fused build+assemble): 256-thread blocks; thread = position for
// the compaction prologue, then (qt, pr) with ONE output row per thread in
// the main loop (2x warps vs round 12 -> occupancy-driven latency hiding).
// grid = (32 pt, 3 c, 8 b). Last block zeroes d_counts + resets d_done.
// ---------------------------------------------------------------------------
__device__ __forceinline__ ull fma2(ull a, ull b, ull c) {
    ull d;
    asm("fma.rn.f32x2 %0, %1, %2, %3;" : "=l"(d) : "l"(a), "l"(b), "l"(c));
    return d;
}

__device__ __forceinline__ ull dup2(float w) {
    uint32_t wb = __float_as_uint(w);
    return ((ull)wb << 32) | (ull)wb;
}

__global__ void __launch_bounds__(256) assemble_kernel(const float* __restrict__ x,
                                                       float* __restrict__ out) {
    __shared__ int s_off[NKB + 1];
    __shared__ int s_pos[NKB * DPOS];
    __shared__ alignas(16) ull s_wt[NKB * DPOS][KPB];
    __shared__ int s_wcnt[8];
    __shared__ int s_base;
    __shared__ int s_last;

    int pt = blockIdx.x;          // 0..31
    int c  = blockIdx.y;
    int b  = blockIdx.z;
    int t  = threadIdx.x;
    int warp = t >> 5, lane = t & 31;

    int flat = (t >> 4) * 65536 + (t & 15) * 64;   // position t as flat offset
    if (t == 0) s_base = 0;
    __syncthreads();

    const float r500 = 1.0f / 500.0f;

    // ---- compaction: thread t = position t; ascending order preserved ----
#pragma unroll
    for (int kb = 0; kb < NKB; kb++) {
        int c0 = d_counts[b][4 * kb + 0][t];
        int c1 = d_counts[b][4 * kb + 1][t];
        int c2 = d_counts[b][4 * kb + 2][t];
        int c3 = d_counts[b][4 * kb + 3][t];
        int any = c0 | c1 | c2 | c3;
        unsigned m = __ballot_sync(0xffffffffu, any != 0);
        if (lane == 0) s_wcnt[warp] = __popc(m);
        __syncthreads();                       // wcnt + prior s_base visible
        int basec = 0, ntot = 0;
#pragma unroll
        for (int wj = 0; wj < 8; wj++) {
            int wc = s_wcnt[wj];
            if (wj < warp) basec += wc;
            ntot += wc;
        }
        int base = s_base;
        if (t == 0) s_off[kb] = base;
        if (any) {
            int slot = base + basec + __popc(m & ((1u << lane) - 1u));
            s_pos[slot] = flat;
            s_wt[slot][0] = dup2((float)c0 * r500);
            s_wt[slot][1] = dup2((float)c1 * r500);
            s_wt[slot][2] = dup2((float)c2 * r500);
            s_wt[slot][3] = dup2((float)c3 * r500);
        }
        __syncthreads();                       // everyone consumed s_base
        if (t == 0) s_base = base + ntot;
    }
    __syncthreads();
    if (t == 0) {
        s_off[NKB] = s_base;
        // all count reads in this block are done -> signal completion
        s_last = (atomicAdd(&d_done, 1) == NBLK - 1) ? 1 : 0;
    }
    __syncthreads();

    // ---- main accumulation: one row per thread ----
    int qt = t & 63;              // q pair: q = 2qt, 2qt+1
    int pr = t >> 6;              // 0..3
    int p0 = pt * 4 + pr;         // single row
    int qc = 2 * qt - 32;         // window col offset (even)
    int pc0 = p0 - 32;

    const float* xb = x + ((size_t)(b * NCH + c) << 20);

#pragma unroll
    for (int kb = 0; kb < NKB; kb++) {
        int e    = s_off[kb];
        int eend = s_off[kb + 1];

        ull acc[KPB];
#pragma unroll
        for (int j = 0; j < KPB; j++) acc[j] = 0ull;

#pragma unroll 1
        for (; e + 2 <= eend; e += 2) {
            int fA = s_pos[e], fB = s_pos[e + 1];
            int colA = (fA & 1023) + qc, colB = (fB & 1023) + qc;
            int rwA = (fA >> 10) + pc0, rwB = (fB >> 10) + pc0;
            ull vA = 0ull, vB = 0ull;
            if ((unsigned)colA < 1024u && (unsigned)rwA < 1024u)
                vA = *(const ull*)(xb + ((size_t)rwA << 10) + colA);
            if ((unsigned)colB < 1024u && (unsigned)rwB < 1024u)
                vB = *(const ull*)(xb + ((size_t)rwB << 10) + colB);
            ulonglong2 wA0 = *(const ulonglong2*)&s_wt[e][0];
            ulonglong2 wA1 = *(const ulonglong2*)&s_wt[e][2];
            ulonglong2 wB0 = *(const ulonglong2*)&s_wt[e + 1][0];
            ulonglong2 wB1 = *(const ulonglong2*)&s_wt[e + 1][2];
            acc[0] = fma2(wA0.x, vA, acc[0]);
            acc[1] = fma2(wA0.y, vA, acc[1]);
            acc[2] = fma2(wA1.x, vA, acc[2]);
            acc[3] = fma2(wA1.y, vA, acc[3]);
            acc[0] = fma2(wB0.x, vB, acc[0]);
            acc[1] = fma2(wB0.y, vB, acc[1]);
            acc[2] = fma2(wB1.x, vB, acc[2]);
            acc[3] = fma2(wB1.y, vB, acc[3]);
        }
        for (; e < eend; e++) {
            int f = s_pos[e];
            int col = (f & 1023) + qc;
            int rw  = (f >> 10) + pc0;
            ull v = 0ull;
            if ((unsigned)col < 1024u && (unsigned)rw < 1024u)
                v = *(const ull*)(xb + ((size_t)rw << 10) + col);
            ulonglong2 w0 = *(const ulonglong2*)&s_wt[e][0];
            ulonglong2 w1 = *(const ulonglong2*)&s_wt[e][2];
            acc[0] = fma2(w0.x, v, acc[0]);
            acc[1] = fma2(w0.y, v, acc[1]);
            acc[2] = fma2(w1.x, v, acc[2]);
            acc[3] = fma2(w1.y, v, acc[3]);
        }

#pragma unroll
        for (int j = 0; j < KPB; j++) {
            int k = kb * KPB + j;
            float* op = out + (((size_t)((b * KSEL + k) * NCH + c)) << 14)
                            + ((size_t)p0 << 7) + 2 * qt;
            *(ull*)op = acc[j];
        }
    }

    // ---- last block restores d_counts (all blocks' reads completed) ----
    if (s_last) {
        int4 z4 = make_int4(0, 0, 0, 0);
        int4* cp = (int4*)&d_counts[0][0][0];
        const int n4 = NB * KSEL * DPOS / 4;     // 8192 int4
#pragma unroll 1
        for (int i = t; i < n4; i += 256) cp[i] = z4;
        if (t == 0) d_done = 0;
    }
}

// ---------------------------------------------------------------------------
extern "C" void kernel_launch(void* const* d_in, const int* in_sizes, int n_in,
                              void* d_out, int out_size) {
    const float* x      = (const float*)d_in[0];
    const float* scores = (const float*)d_in[1];
    if (n_in >= 2 && in_sizes[0] == NB * HGRID * WGRID) {
        const float* tmp = x; x = scores; scores = tmp;
    }
    float* out = (float*)d_out;

    indicator_kernel<<<dim3(125, NB), 128>>>(scores);
    assemble_kernel<<<dim3(32, NCH, NB), 256>>>(x, out);
}

// round 14
// speedup vs baseline: 1.1351x; 1.1351x over previous
#include <cuda_runtime.h>
#include <cstdint>

#define NB      8
#define NCH     3
#define IMG     1024
#define PATCH   128
#define DPOS    256
#define KSEL    16
#define NSAMP   500
#define HGRID   16
#define WGRID   16
#define NKB     4          // k blocks
#define KPB     4          // k per block
#define NBLK    (16 * NCH * NB)   // assemble grid size = 384

typedef unsigned long long ull;

// Persistent device scratch (zero-init at load; the LAST assemble block
// re-zeroes d_counts and resets d_done -> clean state every graph replay).
__device__ __align__(16) int d_counts[NB][KSEL][DPOS];
__device__ int d_done;

// ---------------------------------------------------------------------------
// Threefry-2x32 (20 rounds), JAX partitionable layout:
//   bits[f] = o0 ^ o1 of E(key=(0,42), ctr=(hi=0, lo=f))
// ---------------------------------------------------------------------------
__device__ __forceinline__ uint32_t threefry_bits(uint32_t ctr) {
    const uint32_t K0 = 0u;
    const uint32_t K1 = 42u;
    const uint32_t K2 = 0x1BD11BDAu ^ K0 ^ K1;
    uint32_t x0 = K0;
    uint32_t x1 = ctr + K1;
#define TFR(r) { x0 += x1; x1 = __funnelshift_l(x1, x1, (r)); x1 ^= x0; }
    TFR(13) TFR(15) TFR(26) TFR(6)
    x0 += K1; x1 += K2 + 1u;
    TFR(17) TFR(29) TFR(16) TFR(24)
    x0 += K2; x1 += K0 + 2u;
    TFR(13) TFR(15) TFR(26) TFR(6)
    x0 += K0; x1 += K1 + 3u;
    TFR(17) TFR(29) TFR(16) TFR(24)
    x0 += K1; x1 += K2 + 4u;
    TFR(13) TFR(15) TFR(26) TFR(6)
    x0 += K2; x1 += K0 + 5u;
#undef TFR
    return x0 ^ x1;
}

__device__ __forceinline__ float jax_normal(uint32_t f) {
    uint32_t bits = threefry_bits(f);
    float fl = __uint_as_float((bits >> 9) | 0x3f800000u) - 1.0f;  // [0,1)
    const float lo = -0.99999994f;
    float u = fl * 2.0f + lo;
    u = fmaxf(lo, u);
    return __uint_as_float(0x3fb504f3u) * erfinvf(u);   // sqrt(2)*erfinv
}

// monotone float -> sortable u32 (strictly order-preserving)
__device__ __forceinline__ uint32_t fkey(float v) {
    uint32_t u = __float_as_uint(v);
    return u ^ (uint32_t)(((int)u >> 31) | 0x80000000);
}

// ---------------------------------------------------------------------------
// Kernel 1: perturbed top-K counting; fused normalization; 1 sample/warp,
// REDUX-based selection. grid = (125, NB), block = 128 (4 warps).
// ---------------------------------------------------------------------------
__global__ void indicator_kernel(const float* __restrict__ scores) {
    __shared__ float s_sh[DPOS];
    __shared__ float red[64];
    int b = blockIdx.y;
    int t = threadIdx.x;
    int warp = t >> 5, lane = t & 31;

    // per-batch min/max normalize (redundant per block; trivial)
    float v0 = __ldg(scores + b * DPOS + t);
    float v1 = __ldg(scores + b * DPOS + 128 + t);
    float mn = fminf(v0, v1), mx = fmaxf(v0, v1);
#pragma unroll
    for (int off = 16; off; off >>= 1) {
        mn = fminf(mn, __shfl_down_sync(0xffffffffu, mn, off));
        mx = fmaxf(mx, __shfl_down_sync(0xffffffffu, mx, off));
    }
    if (lane == 0) { red[warp] = mn; red[32 + warp] = mx; }
    __syncthreads();
    if (t == 0) {
        float m0 = red[0], m1 = red[32];
#pragma unroll
        for (int j = 1; j < 4; j++) { m0 = fminf(m0, red[j]); m1 = fmaxf(m1, red[32 + j]); }
        red[0] = m0; red[32] = m1;
    }
    __syncthreads();
    mn = red[0]; mx = red[32];
    float den = (mx - mn) + 1e-5f;
    s_sh[t]       = __fdiv_rn(v0 - mn, den);
    s_sh[t + 128] = __fdiv_rn(v1 - mn, den);
    __syncthreads();

    int sample = blockIdx.x * 4 + warp;            // 0..499
    uint32_t base = (uint32_t)((b * NSAMP + sample) * DPOS);

    uint32_t ka[8];
#pragma unroll
    for (int j = 0; j < 8; j++) {
        int pos = j * 32 + lane;
        float z = jax_normal(base + (uint32_t)pos);
        ka[j] = fkey(__fadd_rn(s_sh[pos], __fmul_rn(z, 0.05f)));
    }

    int sel = 0;
    for (int it = 0; it < KSEL; it++) {
        uint32_t bk = 0u;
        int bp = 0x7fffffff;
#pragma unroll
        for (int j = 0; j < 8; j++) {
            int pos = j * 32 + lane;
            if (ka[j] > bk) { bk = ka[j]; bp = pos; }
        }
        uint32_t m = __reduce_max_sync(0xffffffffu, bk);
        unsigned cand = (bk == m) ? (unsigned)bp : 0x7fffffffu;
        int w = (int)__reduce_min_sync(0xffffffffu, cand);
        int sj = w >> 5;
        if (lane == (w & 31)) {
#pragma unroll
            for (int j = 0; j < 8; j++) if (j == sj) ka[j] = 0u;
        }
        if (lane == it) sel = w;
    }

    // rank = index order among the 16 selections
    int r = 0;
#pragma unroll
    for (int j = 0; j < KSEL; j++) {
        int o = __shfl_sync(0xffffffffu, sel, j);
        if (o < sel) r++;
    }
    if (lane < KSEL) atomicAdd(&d_counts[b][r][sel], 1);
}

// ---------------------------------------------------------------------------
// Kernel 2 (fused build+assemble): 256-thread blocks. Prologue: thread =
// position, single-pass ballot compaction of the 4 k-block sublists.
// Main loop: thread = (q-quad qt' 0..31, row pr 0..7); one LDG.128 covers
// 4 pixels (16B-aligned since col = iw*64 + 4qt' - 32 ≡ 0 mod 4), and the
// 2 LDS.128 weight loads amortize over 4 pixels. grid = (16 pt, 3 c, 8 b).
// Last block zeroes d_counts + resets d_done.
// ---------------------------------------------------------------------------
__device__ __forceinline__ ull fma2(ull a, ull b, ull c) {
    ull d;
    asm("fma.rn.f32x2 %0, %1, %2, %3;" : "=l"(d) : "l"(a), "l"(b), "l"(c));
    return d;
}

__device__ __forceinline__ ull dup2(float w) {
    uint32_t wb = __float_as_uint(w);
    return ((ull)wb << 32) | (ull)wb;
}

__global__ void __launch_bounds__(256) assemble_kernel(const float* __restrict__ x,
                                                       float* __restrict__ out) {
    __shared__ int s_off[NKB + 1];
    __shared__ int s_pos[NKB * DPOS];
    __shared__ alignas(16) ull s_wt[NKB * DPOS][KPB];
    __shared__ int s_wcnt[8];
    __shared__ int s_base;
    __shared__ int s_last;

    int pt = blockIdx.x;          // 0..15 (8 rows each)
    int c  = blockIdx.y;
    int b  = blockIdx.z;
    int t  = threadIdx.x;
    int warp = t >> 5, lane = t & 31;

    int flat = (t >> 4) * 65536 + (t & 15) * 64;   // position t as flat offset
    if (t == 0) s_base = 0;
    __syncthreads();

    const float r500 = 1.0f / 500.0f;

    // ---- compaction: thread t = position t; ascending order preserved ----
#pragma unroll
    for (int kb = 0; kb < NKB; kb++) {
        int c0 = d_counts[b][4 * kb + 0][t];
        int c1 = d_counts[b][4 * kb + 1][t];
        int c2 = d_counts[b][4 * kb + 2][t];
        int c3 = d_counts[b][4 * kb + 3][t];
        int any = c0 | c1 | c2 | c3;
        unsigned m = __ballot_sync(0xffffffffu, any != 0);
        if (lane == 0) s_wcnt[warp] = __popc(m);
        __syncthreads();                       // wcnt + prior s_base visible
        int basec = 0, ntot = 0;
#pragma unroll
        for (int wj = 0; wj < 8; wj++) {
            int wc = s_wcnt[wj];
            if (wj < warp) basec += wc;
            ntot += wc;
        }
        int base = s_base;
        if (t == 0) s_off[kb] = base;
        if (any) {
            int slot = base + basec + __popc(m & ((1u << lane) - 1u));
            s_pos[slot] = flat;
            s_wt[slot][0] = dup2((float)c0 * r500);
            s_wt[slot][1] = dup2((float)c1 * r500);
            s_wt[slot][2] = dup2((float)c2 * r500);
            s_wt[slot][3] = dup2((float)c3 * r500);
        }
        __syncthreads();                       // everyone consumed s_base
        if (t == 0) s_base = base + ntot;
    }
    __syncthreads();
    if (t == 0) {
        s_off[NKB] = s_base;
        // all count reads in this block are done -> signal completion
        s_last = (atomicAdd(&d_done, 1) == NBLK - 1) ? 1 : 0;
    }
    __syncthreads();

    // ---- main accumulation: one q-quad x one row per thread ----
    int qt = t & 31;              // q quad: q = 4qt .. 4qt+3
    int pr = t >> 5;              // 0..7
    int p0 = pt * 8 + pr;         // single row
    int qc = 4 * qt - 32;         // window col offset (multiple of 4)
    int pc0 = p0 - 32;

    const float* xb = x + ((size_t)(b * NCH + c) << 20);

#pragma unroll
    for (int kb = 0; kb < NKB; kb++) {
        int e    = s_off[kb];
        int eend = s_off[kb + 1];

        ull accL[KPB], accH[KPB];
#pragma unroll
        for (int j = 0; j < KPB; j++) { accL[j] = 0ull; accH[j] = 0ull; }

#pragma unroll 1
        for (; e + 2 <= eend; e += 2) {
            int fA = s_pos[e], fB = s_pos[e + 1];
            int colA = (fA & 1023) + qc, colB = (fB & 1023) + qc;
            int rwA = (fA >> 10) + pc0, rwB = (fB >> 10) + pc0;
            ulonglong2 vA = make_ulonglong2(0ull, 0ull);
            ulonglong2 vB = make_ulonglong2(0ull, 0ull);
            // col multiple of 4 => quad [col,col+3] in-bounds iff col < 1024
            if ((unsigned)colA < 1024u && (unsigned)rwA < 1024u)
                vA = *(const ulonglong2*)(xb + ((size_t)rwA << 10) + colA);
            if ((unsigned)colB < 1024u && (unsigned)rwB < 1024u)
                vB = *(const ulonglong2*)(xb + ((size_t)rwB << 10) + colB);
            ulonglong2 wA0 = *(const ulonglong2*)&s_wt[e][0];
            ulonglong2 wA1 = *(const ulonglong2*)&s_wt[e][2];
            ulonglong2 wB0 = *(const ulonglong2*)&s_wt[e + 1][0];
            ulonglong2 wB1 = *(const ulonglong2*)&s_wt[e + 1][2];
            accL[0] = fma2(wA0.x, vA.x, accL[0]); accH[0] = fma2(wA0.x, vA.y, accH[0]);
            accL[1] = fma2(wA0.y, vA.x, accL[1]); accH[1] = fma2(wA0.y, vA.y, accH[1]);
            accL[2] = fma2(wA1.x, vA.x, accL[2]); accH[2] = fma2(wA1.x, vA.y, accH[2]);
            accL[3] = fma2(wA1.y, vA.x, accL[3]); accH[3] = fma2(wA1.y, vA.y, accH[3]);
            accL[0] = fma2(wB0.x, vB.x, accL[0]); accH[0] = fma2(wB0.x, vB.y, accH[0]);
            accL[1] = fma2(wB0.y, vB.x, accL[1]); accH[1] = fma2(wB0.y, vB.y, accH[1]);
            accL[2] = fma2(wB1.x, vB.x, accL[2]); accH[2] = fma2(wB1.x, vB.y, accH[2]);
            accL[3] = fma2(wB1.y, vB.x, accL[3]); accH[3] = fma2(wB1.y, vB.y, accH[3]);
        }
        for (; e < eend; e++) {
            int f = s_pos[e];
            int col = (f & 1023) + qc;
            int rw  = (f >> 10) + pc0;
            ulonglong2 v = make_ulonglong2(0ull, 0ull);
            if ((unsigned)col < 1024u && (unsigned)rw < 1024u)
                v = *(const ulonglong2*)(xb + ((size_t)rw << 10) + col);
            ulonglong2 w0 = *(const ulonglong2*)&s_wt[e][0];
            ulonglong2 w1 = *(const ulonglong2*)&s_wt[e][2];
            accL[0] = fma2(w0.x, v.x, accL[0]); accH[0] = fma2(w0.x, v.y, accH[0]);
            accL[1] = fma2(w0.y, v.x, accL[1]); accH[1] = fma2(w0.y, v.y, accH[1]);
            accL[2] = fma2(w1.x, v.x, accL[2]); accH[2] = fma2(w1.x, v.y, accH[2]);
            accL[3] = fma2(w1.y, v.x, accL[3]); accH[3] = fma2(w1.y, v.y, accH[3]);
        }

#pragma unroll
        for (int j = 0; j < KPB; j++) {
            int k = kb * KPB + j;
            float* op = out + (((size_t)((b * KSEL + k) * NCH + c)) << 14)
                            + ((size_t)p0 << 7) + 4 * qt;
            *(ulonglong2*)op = make_ulonglong2(accL[j], accH[j]);
        }
    }

    // ---- last block restores d_counts (all blocks' reads completed) ----
    if (s_last) {
        int4 z4 = make_int4(0, 0, 0, 0);
        int4* cp = (int4*)&d_counts[0][0][0];
        const int n4 = NB * KSEL * DPOS / 4;     // 8192 int4
#pragma unroll 1
        for (int i = t; i < n4; i += 256) cp[i] = z4;
        if (t == 0) d_done = 0;
    }
}

// ---------------------------------------------------------------------------
extern "C" void kernel_launch(void* const* d_in, const int* in_sizes, int n_in,
                              void* d_out, int out_size) {
    const float* x      = (const float*)d_in[0];
    const float* scores = (const float*)d_in[1];
    if (n_in >= 2 && in_sizes[0] == NB * HGRID * WGRID) {
        const float* tmp = x; x = scores; scores = tmp;
    }
    float* out = (float*)d_out;

    indicator_kernel<<<dim3(125, NB), 128>>>(scores);
    assemble_kernel<<<dim3(16, NCH, NB), 256>>>(x, out);
}